// round 4
// baseline (speedup 1.0000x reference)
#include <cuda_runtime.h>

#define NTOK   16384
#define DIM    2048
#define NE     64
#define KTOP   8
#define ALPHA_C 0.001f

#define TM     128            // tokens per block
#define NT     128            // threads per block (4 warps: one per SMSP)
#define KC     16             // k-chunk
#define KPAD   (KC + 4)       // W tile pitch: lane-stride 20 words -> conflict-free
#define P2     (2*KC + 4)     // H pair-tile pitch (36 floats): 16B-aligned float4 rows
#define NBLK   (NTOK / TM)    // 128 blocks
#define NCHUNK (DIM / KC)     // 128 chunks

// Per-block partials for aux loss (deterministic fixed-order reduce in last block).
__device__ float g_cnt_part[NBLK][NE];
__device__ float g_prob_part[NBLK][NE];
__device__ unsigned int g_sync = 0;   // atomicInc wraps to 0 each launch -> graph-replay safe

struct Tiles {
    float hs2[2][TM / 2][P2];  // token-pair interleaved: element [tp][2k + (t&1)]
    float ws[2][NE][KPAD];     // [expert][k]
};
union Smem {
    Tiles t;
    float logits[TM][NE + 1];  // reused after GEMM
};

typedef unsigned long long u64;

// lane-wise fma.rn: each 32-bit lane rounds exactly like scalar fmaf
__device__ __forceinline__ void ffma2(u64& d, u64 a, u64 b) {
    asm("fma.rn.f32x2 %0, %1, %2, %3;" : "=l"(d) : "l"(a), "l"(b), "l"(d));
}
__device__ __forceinline__ u64 pack2(float x) {   // {x, x}
    u64 r; asm("mov.b64 %0, {%1, %1};" : "=l"(r) : "f"(x)); return r;
}
__device__ __forceinline__ void unpack2(u64 v, float& lo, float& hi) {
    unsigned int a, b;
    asm("mov.b64 {%0, %1}, %2;" : "=r"(a), "=r"(b) : "l"(v));
    lo = __uint_as_float(a); hi = __uint_as_float(b);
}

__device__ __forceinline__ void sts_hpair(float (*hs2)[P2], int row, int kbase, float4 v) {
    const int tp = row >> 1, lane = row & 1;
    hs2[tp][2 * (kbase + 0) + lane] = v.x;
    hs2[tp][2 * (kbase + 1) + lane] = v.y;
    hs2[tp][2 * (kbase + 2) + lane] = v.z;
    hs2[tp][2 * (kbase + 3) + lane] = v.w;
}

__global__ __launch_bounds__(NT, 1)
void gate_kernel(const float* __restrict__ H, const float* __restrict__ W,
                 float* __restrict__ out, int out_size)
{
    __shared__ Smem u;
    __shared__ float rinv[TM];
    __shared__ float sm_cnt[NE];
    __shared__ float pr[2][NE];
    __shared__ float rc[2][NE], rp[2][NE];
    __shared__ unsigned int is_last;

    const int tid = threadIdx.x;
    const int blk = blockIdx.x;
    const int er  = tid & 7;    // experts: er + 8*j, j=0..7 (lane-stride 20 words: conflict-free)
    const int tr  = tid >> 3;   // token pairs tr*4 .. tr*4+3  (tokens tr*8..tr*8+7)

    if (tid < NE) sm_cnt[tid] = 0.f;

    // acc2[i][j]: lanes = tokens {2*(tr*4+i), +1}, expert er+8*j.
    // Each lane accumulates k sequentially 0..2047 -> bit-identical to scalar fmaf chain.
    u64 acc2[4][8];
#pragma unroll
    for (int i = 0; i < 4; i++)
#pragma unroll
        for (int j = 0; j < 8; j++) acc2[i][j] = 0ull;

    const float* Hb = H + (size_t)blk * TM * DIM;

    // loader mapping (128 threads): H 4 float4/thread, W 2 float4/thread per chunk
    const int hr   = tid >> 2;             // base row 0..31 (rows hr, hr+32, hr+64, hr+96)
    const int hc   = (tid & 3) * 4;
    const int wrow = tid >> 1;             // experts 0..63
    const int wc   = (tid & 1) * 8;        // columns wc..wc+3, wc+4..wc+7

    // prologue: chunk 0 -> buf 0
    {
#pragma unroll
        for (int x = 0; x < 4; x++) {
            float4 a = *(const float4*)(Hb + (size_t)(hr + 32 * x) * DIM + hc);
            sts_hpair(u.t.hs2[0], hr + 32 * x, hc, a);
        }
        float4 w0 = *(const float4*)(W + (size_t)wrow * DIM + wc);
        float4 w1 = *(const float4*)(W + (size_t)wrow * DIM + wc + 4);
        *(float4*)&u.t.ws[0][wrow][wc]     = w0;
        *(float4*)&u.t.ws[0][wrow][wc + 4] = w1;
    }

    for (int c = 0; c < NCHUNK; c++) {
        const int b = c & 1;
        float4 hn[4], wn0, wn1;
        const bool more = (c + 1 < NCHUNK);
        if (more) {
            const int kb = (c + 1) * KC;
#pragma unroll
            for (int x = 0; x < 4; x++)
                hn[x] = *(const float4*)(Hb + (size_t)(hr + 32 * x) * DIM + kb + hc);
            wn0 = *(const float4*)(W + (size_t)wrow * DIM + kb + wc);
            wn1 = *(const float4*)(W + (size_t)wrow * DIM + kb + wc + 4);
        }
        __syncthreads();
#pragma unroll
        for (int k4 = 0; k4 < KC; k4 += 4) {
            ulonglong2 h01[4], h23[4];
#pragma unroll
            for (int i = 0; i < 4; i++) {
                const float* p = &u.t.hs2[b][tr * 4 + i][2 * k4];
                h01[i] = *(const ulonglong2*)p;        // pairs for k4, k4+1
                h23[i] = *(const ulonglong2*)(p + 4);  // pairs for k4+2, k4+3
            }
#pragma unroll
            for (int j = 0; j < 8; j++) {
                float4 w = *(const float4*)&u.t.ws[b][er + 8 * j][k4];
                u64 w0 = pack2(w.x), w1 = pack2(w.y), w2 = pack2(w.z), w3 = pack2(w.w);
#pragma unroll
                for (int i = 0; i < 4; i++) {
                    ffma2(acc2[i][j], h01[i].x, w0);
                    ffma2(acc2[i][j], h01[i].y, w1);
                    ffma2(acc2[i][j], h23[i].x, w2);
                    ffma2(acc2[i][j], h23[i].y, w3);
                }
            }
        }
        if (more) {
#pragma unroll
            for (int x = 0; x < 4; x++)
                sts_hpair(u.t.hs2[b ^ 1], hr + 32 * x, hc, hn[x]);
            *(float4*)&u.t.ws[b ^ 1][wrow][wc]     = wn0;
            *(float4*)&u.t.ws[b ^ 1][wrow][wc + 4] = wn1;
        }
    }
    __syncthreads();  // all compute done before union is repurposed

    // -------- logits -> smem --------
#pragma unroll
    for (int i = 0; i < 4; i++)
#pragma unroll
        for (int j = 0; j < 8; j++) {
            float lo, hi;
            unpack2(acc2[i][j], lo, hi);
            const int t0 = 2 * (tr * 4 + i);
            u.logits[t0][er + 8 * j]     = lo;
            u.logits[t0 + 1][er + 8 * j] = hi;
        }
    __syncthreads();

    // -------- per-token softmax + top-8 (one thread per token) --------
    {
        float m = -1e30f;
        for (int e = 0; e < NE; e++) m = fmaxf(m, u.logits[tid][e]);

        float s = 0.f;
        float val[KTOP];
        int   idx[KTOP];
#pragma unroll
        for (int j = 0; j < KTOP; j++) { val[j] = -1.f; idx[j] = 0; }

        for (int e = 0; e < NE; e++) {
            float ex = __expf(u.logits[tid][e] - m);
            u.logits[tid][e] = ex;   // stash exp for mean-prob pass
            s += ex;
            float nv = ex; int ni = e;
#pragma unroll
            for (int j = 0; j < KTOP; j++) {
                if (nv > val[j]) {
                    float tv = val[j]; val[j] = nv; nv = tv;
                    int   ti = idx[j]; idx[j] = ni; ni = ti;
                }
            }
        }
        rinv[tid] = 1.f / s;

        float ts = 0.f;
#pragma unroll
        for (int j = 0; j < KTOP; j++) ts += val[j];
        const float tinv = 1.f / ts;

        const int gt = blk * TM + tid;
        float* ow = out + (size_t)gt * KTOP;
        float* oi = out + (size_t)NTOK * KTOP + (size_t)gt * KTOP;
#pragma unroll
        for (int j = 0; j < KTOP; j++) {
            ow[j] = val[j] * tinv;
            oi[j] = (float)idx[j];
            atomicAdd(&sm_cnt[idx[j]], 1.f);  // integer counts: order-exact
        }
    }
    __syncthreads();

    // -------- per-block mean-prob partial (2 parts x 64 tokens) --------
    {
        const int e = tid & 63;
        const int p = tid >> 6;
        float sacc = 0.f;
        for (int t = p * 64; t < p * 64 + 64; t++)
            sacc += u.logits[t][e] * rinv[t];
        pr[p][e] = sacc;
    }
    __syncthreads();
    if (tid < NE) {
        g_prob_part[blk][tid] = pr[0][tid] + pr[1][tid];
        g_cnt_part[blk][tid]  = sm_cnt[tid];
    }

    // -------- last block finalizes the aux loss (no second launch) --------
    __threadfence();
    if (tid == 0)
        is_last = (atomicInc(&g_sync, NBLK - 1) == NBLK - 1);
    __syncthreads();
    if (is_last) {
        const int e = tid & 63;
        const int p = tid >> 6;       // 2 parts x 64 blocks, fixed order
        float c = 0.f, pm = 0.f;
        for (int b = p * 64; b < p * 64 + 64; b++) {
            c  += g_cnt_part[b][e];
            pm += g_prob_part[b][e];
        }
        rc[p][e] = c; rp[p][e] = pm;
        __syncthreads();
        if (tid == 0) {
            float s = 0.f;
            for (int e2 = 0; e2 < NE; e2++) {
                float C = rc[0][e2] + rc[1][e2];
                float P = rp[0][e2] + rp[1][e2];
                s += (C / (float)(NTOK * KTOP)) * (P / (float)NTOK);
            }
            const int pos = NTOK * KTOP * 2;
            if (pos < out_size) out[pos] = ALPHA_C * (float)NE * s;
        }
    }
}

extern "C" void kernel_launch(void* const* d_in, const int* in_sizes, int n_in,
                              void* d_out, int out_size)
{
    const float* H = (const float*)d_in[0];   // hidden_states (16384, 2048) fp32
    const float* W = (const float*)d_in[1];   // weight (64, 2048) fp32
    float* out = (float*)d_out;

    gate_kernel<<<NBLK, NT>>>(H, W, out, out_size);
}

// round 5
// speedup vs baseline: 1.0156x; 1.0156x over previous
#include <cuda_runtime.h>

#define NTOK   16384
#define DIM    2048
#define NE     64
#define KTOP   8
#define ALPHA_C 0.001f

#define TM     128            // tokens per block
#define NT     256            // threads per block (8 warps; 2 per SMSP)
#define KC     16             // k-chunk
#define PITCH  36             // tile pitch (floats): 16B-aligned rows, conflict-free strides
#define NBLK   (NTOK / TM)    // 128 blocks
#define NCHUNK (DIM / KC)     // 128 chunks

// Per-block partials for aux loss (deterministic fixed-order reduce in last block).
__device__ float g_cnt_part[NBLK][NE];
__device__ float g_prob_part[NBLK][NE];
__device__ unsigned int g_sync = 0;   // atomicInc wraps to 0 each launch -> graph-replay safe

struct Tiles {
    float hs2[2][TM / 2][PITCH];  // token-pair interleaved: [tp][2k + (t&1)]
    float ws2[2][NE][PITCH];      // W duplicated: [e][2k+0] = [e][2k+1] = w[e][k]
};
union Smem {
    Tiles t;
    float logits[TM][NE + 1];     // reused after GEMM
};

typedef unsigned long long u64;

// lane-wise fma.rn: each 32-bit lane rounds exactly like scalar fmaf
__device__ __forceinline__ void ffma2(u64& d, u64 a, u64 b) {
    asm("fma.rn.f32x2 %0, %1, %2, %3;" : "=l"(d) : "l"(a), "l"(b), "l"(d));
}
__device__ __forceinline__ void unpack2(u64 v, float& lo, float& hi) {
    unsigned int a, b;
    asm("mov.b64 {%0, %1}, %2;" : "=r"(a), "=r"(b) : "l"(v));
    lo = __uint_as_float(a); hi = __uint_as_float(b);
}

__device__ __forceinline__ void sts_hpair(float (*hs2)[PITCH], int row, int kbase, float4 v) {
    const int tp = row >> 1, lane = row & 1;
    hs2[tp][2 * (kbase + 0) + lane] = v.x;
    hs2[tp][2 * (kbase + 1) + lane] = v.y;
    hs2[tp][2 * (kbase + 2) + lane] = v.z;
    hs2[tp][2 * (kbase + 3) + lane] = v.w;
}
__device__ __forceinline__ void sts_wdup(float (*ws2)[PITCH], int row, int kbase, float4 v) {
    float4 a = make_float4(v.x, v.x, v.y, v.y);
    float4 b = make_float4(v.z, v.z, v.w, v.w);
    *(float4*)&ws2[row][2 * kbase]     = a;
    *(float4*)&ws2[row][2 * kbase + 4] = b;
}

__global__ __launch_bounds__(NT, 1)
void gate_kernel(const float* __restrict__ H, const float* __restrict__ W,
                 float* __restrict__ out, int out_size)
{
    __shared__ Smem u;
    __shared__ float rinv[TM];
    __shared__ float sm_cnt[NE];
    __shared__ float pr[2][NE];
    __shared__ float rc[2][NE], rp[2][NE];
    __shared__ unsigned int is_last;

    const int tid = threadIdx.x;
    const int blk = blockIdx.x;
    const int er  = tid & 15;   // experts: er + 16*j, j=0..3
    const int tr  = tid >> 4;   // token pairs tr*4 .. tr*4+3 (tokens tr*8..tr*8+7)

    if (tid < NE) sm_cnt[tid] = 0.f;

    // acc2[i][j]: lanes = tokens {2*(tr*4+i), +1}, expert er+16*j.
    // Each lane accumulates k sequentially 0..2047 -> bit-identical to scalar fmaf chain.
    u64 acc2[4][4];
#pragma unroll
    for (int i = 0; i < 4; i++)
#pragma unroll
        for (int j = 0; j < 4; j++) acc2[i][j] = 0ull;

    const float* Hb = H + (size_t)blk * TM * DIM;

    // loader mapping (256 threads): H 2 float4/thread, W 1 float4/thread per chunk
    const int hrow0 = tid >> 2;                 // rows 0..63
    const int hrow1 = (tid + 256) >> 2;         // rows 64..127
    const int hc    = (tid & 3) * 4;
    const int wrow  = tid >> 2;                 // experts 0..63
    const int wc    = (tid & 3) * 4;

    // prologue: chunk 0 -> buf 0
    {
        float4 a = *(const float4*)(Hb + (size_t)hrow0 * DIM + hc);
        float4 b = *(const float4*)(Hb + (size_t)hrow1 * DIM + hc);
        float4 w = *(const float4*)(W  + (size_t)wrow  * DIM + wc);
        sts_hpair(u.t.hs2[0], hrow0, hc, a);
        sts_hpair(u.t.hs2[0], hrow1, hc, b);
        sts_wdup (u.t.ws2[0], wrow,  wc, w);
    }

    for (int c = 0; c < NCHUNK; c++) {
        const int b = c & 1;
        float4 hn0, hn1, wn;
        const bool more = (c + 1 < NCHUNK);
        if (more) {
            const int kb = (c + 1) * KC;
            hn0 = *(const float4*)(Hb + (size_t)hrow0 * DIM + kb + hc);
            hn1 = *(const float4*)(Hb + (size_t)hrow1 * DIM + kb + hc);
            wn  = *(const float4*)(W  + (size_t)wrow  * DIM + kb + wc);
        }
        __syncthreads();

        // software-pipelined k4 loop: slot for k4 loaded one iteration ahead
        ulonglong2 H01[2][4], H23[2][4], W01[2][4], W23[2][4];
#pragma unroll
        for (int i = 0; i < 4; i++) {
            const float* p = &u.t.hs2[b][tr * 4 + i][0];
            H01[0][i] = *(const ulonglong2*)p;
            H23[0][i] = *(const ulonglong2*)(p + 4);
        }
#pragma unroll
        for (int j = 0; j < 4; j++) {
            const float* q = &u.t.ws2[b][er + 16 * j][0];
            W01[0][j] = *(const ulonglong2*)q;        // {{w0,w0},{w1,w1}}
            W23[0][j] = *(const ulonglong2*)(q + 4);  // {{w2,w2},{w3,w3}}
        }
#pragma unroll
        for (int k4 = 0; k4 < KC / 4; k4++) {
            const int cu = k4 & 1, nx = cu ^ 1;
            if (k4 + 1 < KC / 4) {
                const int ko = 8 * (k4 + 1);
#pragma unroll
                for (int i = 0; i < 4; i++) {
                    const float* p = &u.t.hs2[b][tr * 4 + i][ko];
                    H01[nx][i] = *(const ulonglong2*)p;
                    H23[nx][i] = *(const ulonglong2*)(p + 4);
                }
#pragma unroll
                for (int j = 0; j < 4; j++) {
                    const float* q = &u.t.ws2[b][er + 16 * j][ko];
                    W01[nx][j] = *(const ulonglong2*)q;
                    W23[nx][j] = *(const ulonglong2*)(q + 4);
                }
            }
#pragma unroll
            for (int j = 0; j < 4; j++)
#pragma unroll
                for (int i = 0; i < 4; i++) {
                    ffma2(acc2[i][j], H01[cu][i].x, W01[cu][j].x);  // k+0
                    ffma2(acc2[i][j], H01[cu][i].y, W01[cu][j].y);  // k+1
                    ffma2(acc2[i][j], H23[cu][i].x, W23[cu][j].x);  // k+2
                    ffma2(acc2[i][j], H23[cu][i].y, W23[cu][j].y);  // k+3
                }
        }

        if (more) {
            sts_hpair(u.t.hs2[b ^ 1], hrow0, hc, hn0);
            sts_hpair(u.t.hs2[b ^ 1], hrow1, hc, hn1);
            sts_wdup (u.t.ws2[b ^ 1], wrow,  wc, wn);
        }
    }
    __syncthreads();  // all compute done before union is repurposed

    // -------- logits -> smem --------
#pragma unroll
    for (int i = 0; i < 4; i++)
#pragma unroll
        for (int j = 0; j < 4; j++) {
            float lo, hi;
            unpack2(acc2[i][j], lo, hi);
            const int t0 = 2 * (tr * 4 + i);
            u.logits[t0][er + 16 * j]     = lo;
            u.logits[t0 + 1][er + 16 * j] = hi;
        }
    __syncthreads();

    // -------- per-token softmax + top-8 (one thread per token) --------
    if (tid < TM) {
        float m = -1e30f;
        for (int e = 0; e < NE; e++) m = fmaxf(m, u.logits[tid][e]);

        float s = 0.f;
        float val[KTOP];
        int   idx[KTOP];
#pragma unroll
        for (int j = 0; j < KTOP; j++) { val[j] = -1.f; idx[j] = 0; }

        for (int e = 0; e < NE; e++) {
            float ex = __expf(u.logits[tid][e] - m);
            u.logits[tid][e] = ex;   // stash exp for mean-prob pass
            s += ex;
            float nv = ex; int ni = e;
#pragma unroll
            for (int j = 0; j < KTOP; j++) {
                if (nv > val[j]) {
                    float tv = val[j]; val[j] = nv; nv = tv;
                    int   ti = idx[j]; idx[j] = ni; ni = ti;
                }
            }
        }
        rinv[tid] = 1.f / s;

        float ts = 0.f;
#pragma unroll
        for (int j = 0; j < KTOP; j++) ts += val[j];
        const float tinv = 1.f / ts;

        const int gt = blk * TM + tid;
        float* ow = out + (size_t)gt * KTOP;
        float* oi = out + (size_t)NTOK * KTOP + (size_t)gt * KTOP;
#pragma unroll
        for (int j = 0; j < KTOP; j++) {
            ow[j] = val[j] * tinv;
            oi[j] = (float)idx[j];
            atomicAdd(&sm_cnt[idx[j]], 1.f);  // integer counts: order-exact
        }
    }
    __syncthreads();

    // -------- per-block mean-prob partial (4 parts x 32 tokens) --------
    {
        const int e = tid & 63;
        const int p = tid >> 6;
        float sacc = 0.f;
        for (int t = p * 32; t < p * 32 + 32; t++)
            sacc += u.logits[t][e] * rinv[t];
        if (p < 2) pr[p][e] = sacc;
        __syncthreads();
        if (p >= 2) { pr[p - 2][e] += sacc; }  // note: needs ordering; do in two steps
    }
    __syncthreads();
    if (tid < NE) {
        g_prob_part[blk][tid] = pr[0][tid] + pr[1][tid];
        g_cnt_part[blk][tid]  = sm_cnt[tid];
    }

    // -------- last block finalizes the aux loss (no second launch) --------
    __threadfence();
    if (tid == 0)
        is_last = (atomicInc(&g_sync, NBLK - 1) == NBLK - 1);
    __syncthreads();
    if (is_last && tid < TM) {
        const int e = tid & 63;
        const int p = tid >> 6;       // 2 parts x 64 blocks, fixed order
        float c = 0.f, pm = 0.f;
        for (int b = p * 64; b < p * 64 + 64; b++) {
            c  += g_cnt_part[b][e];
            pm += g_prob_part[b][e];
        }
        rc[p][e] = c; rp[p][e] = pm;
    }
    __syncthreads();
    if (is_last && tid == 0) {
        float s = 0.f;
        for (int e2 = 0; e2 < NE; e2++) {
            float C = rc[0][e2] + rc[1][e2];
            float P = rp[0][e2] + rp[1][e2];
            s += (C / (float)(NTOK * KTOP)) * (P / (float)NTOK);
        }
        const int pos = NTOK * KTOP * 2;
        if (pos < out_size) out[pos] = ALPHA_C * (float)NE * s;
    }
}

extern "C" void kernel_launch(void* const* d_in, const int* in_sizes, int n_in,
                              void* d_out, int out_size)
{
    const float* H = (const float*)d_in[0];   // hidden_states (16384, 2048) fp32
    const float* W = (const float*)d_in[1];   // weight (64, 2048) fp32
    float* out = (float*)d_out;

    gate_kernel<<<NBLK, NT>>>(H, W, out, out_size);
}

// round 6
// speedup vs baseline: 1.0498x; 1.0337x over previous
#include <cuda_runtime.h>

#define NTOK   16384
#define DIM    2048
#define NE     64
#define KTOP   8
#define ALPHA_C 0.001f

#define TM     64             // tokens per block
#define NT     128            // threads per block (4 warps); 2 blocks resident per SM
#define KC     32             // k-chunk (64 chunks -> 64 barriers per block)
#define WPITCH (KC + 4)       // W tile pitch 36: lane-stride 4 banks, conflict-free
#define HPITCH (2*KC + 4)     // H pair-tile pitch 68: 16B-aligned float4 rows
#define NBLK   (NTOK / TM)    // 256 blocks
#define NCHUNK (DIM / KC)     // 64 chunks

// Per-block partials for aux loss (deterministic fixed-order reduce in last block).
__device__ float g_cnt_part[NBLK][NE];
__device__ float g_prob_part[NBLK][NE];
__device__ unsigned int g_sync = 0;   // atomicInc wraps to 0 each launch -> graph-replay safe

struct Tiles {
    float hs2[2][TM / 2][HPITCH];  // token-pair interleaved: [tp][2k + (t&1)]
    float ws[2][NE][WPITCH];       // [expert][k]
};
union Smem {
    Tiles t;
    float logits[TM][NE + 1];      // reused after GEMM
};

typedef unsigned long long u64;

// lane-wise fma.rn: each 32-bit lane rounds exactly like scalar fmaf
__device__ __forceinline__ void ffma2(u64& d, u64 a, u64 b) {
    asm("fma.rn.f32x2 %0, %1, %2, %3;" : "=l"(d) : "l"(a), "l"(b), "l"(d));
}
__device__ __forceinline__ u64 pack2(float x) {   // {x, x}
    u64 r; asm("mov.b64 %0, {%1, %1};" : "=l"(r) : "f"(x)); return r;
}
__device__ __forceinline__ void unpack2(u64 v, float& lo, float& hi) {
    unsigned int a, b;
    asm("mov.b64 {%0, %1}, %2;" : "=r"(a), "=r"(b) : "l"(v));
    lo = __uint_as_float(a); hi = __uint_as_float(b);
}

__device__ __forceinline__ void sts_hpair(float (*hs2)[HPITCH], int row, int kbase, float4 v) {
    const int tp = row >> 1, lane = row & 1;
    hs2[tp][2 * (kbase + 0) + lane] = v.x;
    hs2[tp][2 * (kbase + 1) + lane] = v.y;
    hs2[tp][2 * (kbase + 2) + lane] = v.z;
    hs2[tp][2 * (kbase + 3) + lane] = v.w;
}

__global__ __launch_bounds__(NT, 2)
void gate_kernel(const float* __restrict__ H, const float* __restrict__ W,
                 float* __restrict__ out, int out_size)
{
    __shared__ Smem u;
    __shared__ float rinv[TM];
    __shared__ float sm_cnt[NE];
    __shared__ float pr[2][NE];
    __shared__ float rc[2][NE], rp[2][NE];
    __shared__ unsigned int is_last;

    const int tid = threadIdx.x;
    const int blk = blockIdx.x;
    const int er  = tid & 15;   // experts: er + 16*j, j=0..3
    const int tr  = tid >> 4;   // 0..7: token pairs tr*4 .. tr*4+3 (tokens tr*8..tr*8+7)

    if (tid < NE) sm_cnt[tid] = 0.f;

    // acc2[i][j]: lanes = tokens {2*(tr*4+i), +1}, expert er+16*j.
    // Each lane accumulates k sequentially 0..2047 -> bit-identical to R3/R0 fmaf chain.
    u64 acc2[4][4];
#pragma unroll
    for (int i = 0; i < 4; i++)
#pragma unroll
        for (int j = 0; j < 4; j++) acc2[i][j] = 0ull;

    const float* Hb = H + (size_t)blk * TM * DIM;

    // loader mapping (128 threads, KC=32): H 4 float4/thread, W 4 float4/thread per chunk
    const int lrow = tid >> 1;             // 0..63 (token row / expert row)
    const int lc   = (tid & 1) * 16;       // float col base: 0 or 16

    // prologue: chunk 0 -> buf 0
    {
#pragma unroll
        for (int x = 0; x < 4; x++) {
            float4 a = *(const float4*)(Hb + (size_t)lrow * DIM + lc + 4 * x);
            sts_hpair(u.t.hs2[0], lrow, lc + 4 * x, a);
        }
#pragma unroll
        for (int x = 0; x < 4; x++) {
            float4 w = *(const float4*)(W + (size_t)lrow * DIM + lc + 4 * x);
            *(float4*)&u.t.ws[0][lrow][lc + 4 * x] = w;
        }
    }

    for (int c = 0; c < NCHUNK; c++) {
        const int b = c & 1;
        float4 hn[4], wn[4];
        const bool more = (c + 1 < NCHUNK);
        if (more) {
            const int kb = (c + 1) * KC;
#pragma unroll
            for (int x = 0; x < 4; x++)
                hn[x] = *(const float4*)(Hb + (size_t)lrow * DIM + kb + lc + 4 * x);
#pragma unroll
            for (int x = 0; x < 4; x++)
                wn[x] = *(const float4*)(W + (size_t)lrow * DIM + kb + lc + 4 * x);
        }
        __syncthreads();  // prev STS to buf b visible; prev compute on b^1 done
#pragma unroll
        for (int k4 = 0; k4 < KC; k4 += 4) {
            ulonglong2 h01[4], h23[4];
#pragma unroll
            for (int i = 0; i < 4; i++) {
                const float* p = &u.t.hs2[b][tr * 4 + i][2 * k4];
                h01[i] = *(const ulonglong2*)p;        // token pairs for k4, k4+1
                h23[i] = *(const ulonglong2*)(p + 4);  // token pairs for k4+2, k4+3
            }
#pragma unroll
            for (int j = 0; j < 4; j++) {
                float4 w = *(const float4*)&u.t.ws[b][er + 16 * j][k4];
                u64 w0 = pack2(w.x), w1 = pack2(w.y), w2 = pack2(w.z), w3 = pack2(w.w);
#pragma unroll
                for (int i = 0; i < 4; i++) {
                    ffma2(acc2[i][j], h01[i].x, w0);
                    ffma2(acc2[i][j], h01[i].y, w1);
                    ffma2(acc2[i][j], h23[i].x, w2);
                    ffma2(acc2[i][j], h23[i].y, w3);
                }
            }
        }
        if (more) {
#pragma unroll
            for (int x = 0; x < 4; x++)
                sts_hpair(u.t.hs2[b ^ 1], lrow, lc + 4 * x, hn[x]);
#pragma unroll
            for (int x = 0; x < 4; x++)
                *(float4*)&u.t.ws[b ^ 1][lrow][lc + 4 * x] = wn[x];
        }
    }
    __syncthreads();  // all compute done before union is repurposed

    // -------- logits -> smem --------
#pragma unroll
    for (int i = 0; i < 4; i++)
#pragma unroll
        for (int j = 0; j < 4; j++) {
            float lo, hi;
            unpack2(acc2[i][j], lo, hi);
            const int t0 = 2 * (tr * 4 + i);
            u.logits[t0][er + 16 * j]     = lo;
            u.logits[t0 + 1][er + 16 * j] = hi;
        }
    __syncthreads();

    // -------- per-token softmax + top-8 (one thread per token) --------
    if (tid < TM) {
        float m = -1e30f;
        for (int e = 0; e < NE; e++) m = fmaxf(m, u.logits[tid][e]);

        float s = 0.f;
        float val[KTOP];
        int   idx[KTOP];
#pragma unroll
        for (int j = 0; j < KTOP; j++) { val[j] = -1.f; idx[j] = 0; }

        for (int e = 0; e < NE; e++) {
            float ex = __expf(u.logits[tid][e] - m);
            u.logits[tid][e] = ex;   // stash exp for mean-prob pass
            s += ex;
            float nv = ex; int ni = e;
#pragma unroll
            for (int j = 0; j < KTOP; j++) {
                if (nv > val[j]) {
                    float tv = val[j]; val[j] = nv; nv = tv;
                    int   ti = idx[j]; idx[j] = ni; ni = ti;
                }
            }
        }
        rinv[tid] = 1.f / s;

        float ts = 0.f;
#pragma unroll
        for (int j = 0; j < KTOP; j++) ts += val[j];
        const float tinv = 1.f / ts;

        const int gt = blk * TM + tid;
        float* ow = out + (size_t)gt * KTOP;
        float* oi = out + (size_t)NTOK * KTOP + (size_t)gt * KTOP;
#pragma unroll
        for (int j = 0; j < KTOP; j++) {
            ow[j] = val[j] * tinv;
            oi[j] = (float)idx[j];
            atomicAdd(&sm_cnt[idx[j]], 1.f);  // integer counts: order-exact
        }
    }
    __syncthreads();

    // -------- per-block mean-prob partial (2 parts x 32 tokens) --------
    {
        const int e = tid & 63;
        const int p = tid >> 6;
        float sacc = 0.f;
        for (int t = p * 32; t < p * 32 + 32; t++)
            sacc += u.logits[t][e] * rinv[t];
        pr[p][e] = sacc;
    }
    __syncthreads();
    if (tid < NE) {
        g_prob_part[blk][tid] = pr[0][tid] + pr[1][tid];
        g_cnt_part[blk][tid]  = sm_cnt[tid];
    }

    // -------- last block finalizes the aux loss (no second launch) --------
    __threadfence();
    if (tid == 0)
        is_last = (atomicInc(&g_sync, NBLK - 1) == NBLK - 1);
    __syncthreads();
    if (is_last) {
        const int e = tid & 63;
        const int p = tid >> 6;       // 2 parts x 128 blocks, fixed order
        float c = 0.f, pm = 0.f;
        for (int b = p * 128; b < p * 128 + 128; b++) {
            c  += g_cnt_part[b][e];
            pm += g_prob_part[b][e];
        }
        rc[p][e] = c; rp[p][e] = pm;
        __syncthreads();
        if (tid == 0) {
            float s = 0.f;
            for (int e2 = 0; e2 < NE; e2++) {
                float C = rc[0][e2] + rc[1][e2];
                float P = rp[0][e2] + rp[1][e2];
                s += (C / (float)(NTOK * KTOP)) * (P / (float)NTOK);
            }
            const int pos = NTOK * KTOP * 2;
            if (pos < out_size) out[pos] = ALPHA_C * (float)NE * s;
        }
    }
}

extern "C" void kernel_launch(void* const* d_in, const int* in_sizes, int n_in,
                              void* d_out, int out_size)
{
    const float* H = (const float*)d_in[0];   // hidden_states (16384, 2048) fp32
    const float* W = (const float*)d_in[1];   // weight (64, 2048) fp32
    float* out = (float*)d_out;

    gate_kernel<<<NBLK, NT>>>(H, W, out, out_size);
}

// round 7
// speedup vs baseline: 1.1211x; 1.0679x over previous
#include <cuda_runtime.h>

#define NTOK   16384
#define DIM    2048
#define NE     64
#define KTOP   8
#define ALPHA_C 0.001f

#define TM     64             // tokens per block
#define NT     128            // threads per block (4 warps); 2 blocks resident per SM
#define KC     32             // k-chunk (64 chunks -> 64 barriers per block)
#define WPITCH (KC + 4)       // W tile pitch 36: lane-stride 4 banks, conflict-free
#define HPITCH (2*KC + 4)     // H pair-tile pitch 68: 16B-aligned float4 rows
#define NBLK   (NTOK / TM)    // 256 blocks
#define NCHUNK (DIM / KC)     // 64 chunks

// Per-block partials for aux loss (deterministic fixed-order reduce in last block).
__device__ float g_cnt_part[NBLK][NE];
__device__ float g_prob_part[NBLK][NE];
__device__ unsigned int g_sync = 0;   // atomicInc wraps to 0 each launch -> graph-replay safe

struct Tiles {
    float hs2[2][TM / 2][HPITCH];  // token-pair interleaved: [tp][2k + (t&1)]
    float ws[2][NE][WPITCH];       // [expert][k]
};
union Smem {
    Tiles t;
    float logits[TM][NE + 1];      // reused after GEMM
};

typedef unsigned long long u64;

// lane-wise fma.rn: each 32-bit lane rounds exactly like scalar fmaf
__device__ __forceinline__ void ffma2(u64& d, u64 a, u64 b) {
    asm("fma.rn.f32x2 %0, %1, %2, %3;" : "=l"(d) : "l"(a), "l"(b), "l"(d));
}
__device__ __forceinline__ u64 pack2(float x) {   // {x, x}
    u64 r; asm("mov.b64 %0, {%1, %1};" : "=l"(r) : "f"(x)); return r;
}
__device__ __forceinline__ void unpack2(u64 v, float& lo, float& hi) {
    unsigned int a, b;
    asm("mov.b64 {%0, %1}, %2;" : "=r"(a), "=r"(b) : "l"(v));
    lo = __uint_as_float(a); hi = __uint_as_float(b);
}

__device__ __forceinline__ void sts_hpair(float (*hs2)[HPITCH], int row, int kbase, float4 v) {
    const int tp = row >> 1, lane = row & 1;
    hs2[tp][2 * (kbase + 0) + lane] = v.x;
    hs2[tp][2 * (kbase + 1) + lane] = v.y;
    hs2[tp][2 * (kbase + 2) + lane] = v.z;
    hs2[tp][2 * (kbase + 3) + lane] = v.w;
}

__global__ __launch_bounds__(NT, 2)
void gate_kernel(const float* __restrict__ H, const float* __restrict__ W,
                 float* __restrict__ out, int out_size)
{
    __shared__ Smem u;
    __shared__ float rinv[TM];
    __shared__ float sm_cnt[NE];
    __shared__ float pr[2][NE];
    __shared__ float rc[2][NE], rp[2][NE];
    __shared__ unsigned int is_last;

    const int tid = threadIdx.x;
    const int blk = blockIdx.x;
    const int er  = tid & 15;   // experts: er + 16*j, j=0..3
    const int tr  = tid >> 4;   // 0..7: token pairs tr*4 .. tr*4+3 (tokens tr*8..tr*8+7)

    if (tid < NE) sm_cnt[tid] = 0.f;

    // acc2[i][j]: lanes = tokens {2*(tr*4+i), +1}, expert er+16*j.
    // Each lane accumulates k sequentially 0..2047 -> bit-identical to R3/R0 fmaf chain.
    u64 acc2[4][4];
#pragma unroll
    for (int i = 0; i < 4; i++)
#pragma unroll
        for (int j = 0; j < 4; j++) acc2[i][j] = 0ull;

    const float* Hb = H + (size_t)blk * TM * DIM;

    // loader mapping (128 threads, KC=32): H 4 float4/thread, W 4 float4/thread per chunk
    const int lrow = tid >> 1;             // 0..63 (token row / expert row)
    const int lc   = (tid & 1) * 16;       // float col base: 0 or 16

    // prologue: chunk 0 -> buf 0
    {
#pragma unroll
        for (int x = 0; x < 4; x++) {
            float4 a = *(const float4*)(Hb + (size_t)lrow * DIM + lc + 4 * x);
            sts_hpair(u.t.hs2[0], lrow, lc + 4 * x, a);
        }
#pragma unroll
        for (int x = 0; x < 4; x++) {
            float4 w = *(const float4*)(W + (size_t)lrow * DIM + lc + 4 * x);
            *(float4*)&u.t.ws[0][lrow][lc + 4 * x] = w;
        }
    }

    for (int c = 0; c < NCHUNK; c++) {
        const int b = c & 1;
        float4 hn[4], wn[4];
        const bool more = (c + 1 < NCHUNK);
        if (more) {
            const int kb = (c + 1) * KC;
#pragma unroll
            for (int x = 0; x < 4; x++)
                hn[x] = *(const float4*)(Hb + (size_t)lrow * DIM + kb + lc + 4 * x);
#pragma unroll
            for (int x = 0; x < 4; x++)
                wn[x] = *(const float4*)(W + (size_t)lrow * DIM + kb + lc + 4 * x);
        }
        __syncthreads();  // prev STS to buf b visible; prev compute on b^1 done
#pragma unroll
        for (int k4 = 0; k4 < KC; k4 += 4) {
            ulonglong2 h01[4], h23[4];
#pragma unroll
            for (int i = 0; i < 4; i++) {
                const float* p = &u.t.hs2[b][tr * 4 + i][2 * k4];
                h01[i] = *(const ulonglong2*)p;        // token pairs for k4, k4+1
                h23[i] = *(const ulonglong2*)(p + 4);  // token pairs for k4+2, k4+3
            }
            float4 w[4];
#pragma unroll
            for (int j = 0; j < 4; j++)
                w[j] = *(const float4*)&u.t.ws[b][er + 16 * j][k4];

            // k-major FMA order: per k-step, 16 FFMA2 over distinct accumulators
            // (no RAW chains; h operand reused across the j-inner loop).
            // Per-acc k order stays k+0,k+1,k+2,k+3 -> bit-identical logits.
            u64 wp[4];
#pragma unroll
            for (int j = 0; j < 4; j++) wp[j] = pack2(w[j].x);   // k+0
#pragma unroll
            for (int i = 0; i < 4; i++)
#pragma unroll
                for (int j = 0; j < 4; j++) ffma2(acc2[i][j], h01[i].x, wp[j]);
#pragma unroll
            for (int j = 0; j < 4; j++) wp[j] = pack2(w[j].y);   // k+1
#pragma unroll
            for (int i = 0; i < 4; i++)
#pragma unroll
                for (int j = 0; j < 4; j++) ffma2(acc2[i][j], h01[i].y, wp[j]);
#pragma unroll
            for (int j = 0; j < 4; j++) wp[j] = pack2(w[j].z);   // k+2
#pragma unroll
            for (int i = 0; i < 4; i++)
#pragma unroll
                for (int j = 0; j < 4; j++) ffma2(acc2[i][j], h23[i].x, wp[j]);
#pragma unroll
            for (int j = 0; j < 4; j++) wp[j] = pack2(w[j].w);   // k+3
#pragma unroll
            for (int i = 0; i < 4; i++)
#pragma unroll
                for (int j = 0; j < 4; j++) ffma2(acc2[i][j], h23[i].y, wp[j]);
        }
        if (more) {
#pragma unroll
            for (int x = 0; x < 4; x++)
                sts_hpair(u.t.hs2[b ^ 1], lrow, lc + 4 * x, hn[x]);
#pragma unroll
            for (int x = 0; x < 4; x++)
                *(float4*)&u.t.ws[b ^ 1][lrow][lc + 4 * x] = wn[x];
        }
    }
    __syncthreads();  // all compute done before union is repurposed

    // -------- logits -> smem --------
#pragma unroll
    for (int i = 0; i < 4; i++)
#pragma unroll
        for (int j = 0; j < 4; j++) {
            float lo, hi;
            unpack2(acc2[i][j], lo, hi);
            const int t0 = 2 * (tr * 4 + i);
            u.logits[t0][er + 16 * j]     = lo;
            u.logits[t0 + 1][er + 16 * j] = hi;
        }
    __syncthreads();

    // -------- per-token softmax + top-8 (one thread per token) --------
    if (tid < TM) {
        float m = -1e30f;
        for (int e = 0; e < NE; e++) m = fmaxf(m, u.logits[tid][e]);

        float s = 0.f;
        float val[KTOP];
        int   idx[KTOP];
#pragma unroll
        for (int j = 0; j < KTOP; j++) { val[j] = -1.f; idx[j] = 0; }

        for (int e = 0; e < NE; e++) {
            float ex = __expf(u.logits[tid][e] - m);
            u.logits[tid][e] = ex;   // stash exp for mean-prob pass
            s += ex;
            float nv = ex; int ni = e;
#pragma unroll
            for (int j = 0; j < KTOP; j++) {
                if (nv > val[j]) {
                    float tv = val[j]; val[j] = nv; nv = tv;
                    int   ti = idx[j]; idx[j] = ni; ni = ti;
                }
            }
        }
        rinv[tid] = 1.f / s;

        float ts = 0.f;
#pragma unroll
        for (int j = 0; j < KTOP; j++) ts += val[j];
        const float tinv = 1.f / ts;

        const int gt = blk * TM + tid;
        float* ow = out + (size_t)gt * KTOP;
        float* oi = out + (size_t)NTOK * KTOP + (size_t)gt * KTOP;
#pragma unroll
        for (int j = 0; j < KTOP; j++) {
            ow[j] = val[j] * tinv;
            oi[j] = (float)idx[j];
            atomicAdd(&sm_cnt[idx[j]], 1.f);  // integer counts: order-exact
        }
    }
    __syncthreads();

    // -------- per-block mean-prob partial (2 parts x 32 tokens) --------
    {
        const int e = tid & 63;
        const int p = tid >> 6;
        float sacc = 0.f;
        for (int t = p * 32; t < p * 32 + 32; t++)
            sacc += u.logits[t][e] * rinv[t];
        pr[p][e] = sacc;
    }
    __syncthreads();
    if (tid < NE) {
        g_prob_part[blk][tid] = pr[0][tid] + pr[1][tid];
        g_cnt_part[blk][tid]  = sm_cnt[tid];
    }

    // -------- last block finalizes the aux loss (no second launch) --------
    __threadfence();
    if (tid == 0)
        is_last = (atomicInc(&g_sync, NBLK - 1) == NBLK - 1);
    __syncthreads();
    if (is_last) {
        const int e = tid & 63;
        const int p = tid >> 6;       // 2 parts x 128 blocks, fixed order
        float c = 0.f, pm = 0.f;
        for (int b = p * 128; b < p * 128 + 128; b++) {
            c  += g_cnt_part[b][e];
            pm += g_prob_part[b][e];
        }
        rc[p][e] = c; rp[p][e] = pm;
        __syncthreads();
        if (tid == 0) {
            float s = 0.f;
            for (int e2 = 0; e2 < NE; e2++) {
                float C = rc[0][e2] + rc[1][e2];
                float P = rp[0][e2] + rp[1][e2];
                s += (C / (float)(NTOK * KTOP)) * (P / (float)NTOK);
            }
            const int pos = NTOK * KTOP * 2;
            if (pos < out_size) out[pos] = ALPHA_C * (float)NE * s;
        }
    }
}

extern "C" void kernel_launch(void* const* d_in, const int* in_sizes, int n_in,
                              void* d_out, int out_size)
{
    const float* H = (const float*)d_in[0];   // hidden_states (16384, 2048) fp32
    const float* W = (const float*)d_in[1];   // weight (64, 2048) fp32
    float* out = (float*)d_out;

    gate_kernel<<<NBLK, NT>>>(H, W, out, out_size);
}